// round 17
// baseline (speedup 1.0000x reference)
#include <cuda_runtime.h>
#include <cuda_bf16.h>
#include <cuda_fp16.h>
#include <cstdint>

// Problem constants
#define VCODES 8192
#define DDIM   256
#define MROWS  32768      // 8 * 16*16*16
#define SPAT   4096       // 16*16*16
#define NTILES 64         // VCODES / 128

// Output layout (concatenated f32)
#define O_QUANT 0ul
#define O_IDX   8388608ul
#define O_QD    8421376ul
#define O_NEWN  8421377ul
#define O_ZAVG  8429569ul
#define O_NEWW  10526721ul

#define MARGIN 3.0f

// ---------------------------------------------------------------------------
// Scratch (device globals; no allocations allowed)
__device__ int   g_idx[MROWS];
__device__ float g_counts[VCODES];
__device__ __align__(16) float g_encsum[VCODES * DDIM];
__device__ float g_wsq[VCODES];
__device__ float g_sumN;
__device__ float g_qd;
__device__ unsigned g_tilemax[MROWS * NTILES];   // monotone-encoded fp32 per (row, tile)
__device__ __align__(16) __half g_ahf[MROWS * DDIM];   // flat x, fp16
__device__ __align__(16) __half g_whf[VCODES * DDIM];  // weight, fp16
__device__ __nv_bfloat16 g_scores[(size_t)MROWS * VCODES];  // coarse scores

// ---------------------------------------------------------------------------
__device__ __forceinline__ uint32_t smem_u32(const void* p) {
    uint32_t a;
    asm("{ .reg .u64 t; cvta.to.shared.u64 t, %1; cvt.u32.u64 %0, t; }" : "=r"(a) : "l"(p));
    return a;
}
__device__ __forceinline__ void cp16(uint32_t dst, const void* src) {
    asm volatile("cp.async.cg.shared.global [%0], [%1], 16;" :: "r"(dst), "l"(src) : "memory");
}
__device__ __forceinline__ void ldm4(uint32_t* r, uint32_t addr) {
    asm volatile("ldmatrix.sync.aligned.m8n8.x4.shared.b16 {%0,%1,%2,%3}, [%4];"
                 : "=r"(r[0]), "=r"(r[1]), "=r"(r[2]), "=r"(r[3]) : "r"(addr));
}
// fp16-accumulate HMMA
__device__ __forceinline__ void mma16816h(uint32_t* c, const uint32_t* a, const uint32_t* b) {
    asm volatile(
        "mma.sync.aligned.m16n8k16.row.col.f16.f16.f16.f16 "
        "{%0,%1}, {%2,%3,%4,%5}, {%6,%7}, {%0,%1};"
        : "+r"(c[0]), "+r"(c[1])
        : "r"(a[0]), "r"(a[1]), "r"(a[2]), "r"(a[3]), "r"(b[0]), "r"(b[1]));
}
__device__ __forceinline__ void st_cs32(void* p, uint32_t v) {
    asm volatile("st.global.cs.b32 [%0], %1;" :: "l"(p), "r"(v) : "memory");
}
// vector fp32 reduction (sm_90+)
__device__ __forceinline__ void red4(float* p, float a, float b, float c, float d) {
    asm volatile("red.global.add.v4.f32 [%0], {%1, %2, %3, %4};"
                 :: "l"(p), "f"(a), "f"(b), "f"(c), "f"(d) : "memory");
}
__device__ __forceinline__ unsigned enc_f(float f) {
    unsigned u = __float_as_uint(f);
    return (u & 0x80000000u) ? ~u : (u | 0x80000000u);
}
__device__ __forceinline__ float dec_f(unsigned u) {
    unsigned b = (u & 0x80000000u) ? (u & 0x7FFFFFFFu) : ~u;
    return __uint_as_float(b);
}

// ---------------------------------------------------------------------------
// Fused prep: role by block range.
//   q in [0, 512)       : zero encsum (float4 x4 per thread)
//   q in [512, 544)     : zero counts (32 blocks x 256 = 8192)
//   q == 544            : qd = 0, sum(N)
//   q in [545, 1569)    : weight -> fp16 (vectorized), wsq
//   q in [1569, 9761)   : x transpose -> fp16 rows
__global__ void k_prep(const float* __restrict__ x, const float* __restrict__ w,
                       const float* __restrict__ N) {
    __shared__ float t[32][33];
    __shared__ float red[8];
    int q = blockIdx.x;
    int tid = threadIdx.x;
    if (q < 512) {
        float4* p = reinterpret_cast<float4*>(g_encsum) + (size_t)q * 1024 + tid;
        float4 z = {0.f, 0.f, 0.f, 0.f};
#pragma unroll
        for (int i = 0; i < 4; ++i) p[i * 256] = z;
        return;
    }
    if (q < 544) {
        g_counts[(q - 512) * 256 + tid] = 0.0f;   // 32 blocks -> all 8192
        return;
    }
    if (q == 544) {                               // qd + sum(N)
        float s = 0.0f;
        for (int i = tid; i < VCODES; i += 256) s += N[i];
#pragma unroll
        for (int o = 16; o; o >>= 1) s += __shfl_xor_sync(0xFFFFFFFFu, s, o);
        if ((tid & 31) == 0) red[tid >> 5] = s;
        __syncthreads();
        if (tid == 0) {
            float tt = 0.0f;
#pragma unroll
            for (int i = 0; i < 8; ++i) tt += red[i];
            g_sumN = tt;
            g_qd = 0.0f;
        }
        return;
    }
    if (q < 1569) {                               // weight prep: warp per code
        int gid = (q - 545) * 256 + tid;
        int v = gid >> 5, lane = gid & 31;
        const float* row = w + (size_t)v * DDIM;
        float4 f0 = __ldg(reinterpret_cast<const float4*>(row + lane * 8));
        float4 f1 = __ldg(reinterpret_cast<const float4*>(row + lane * 8 + 4));
        float s = f0.x*f0.x + f0.y*f0.y + f0.z*f0.z + f0.w*f0.w
                + f1.x*f1.x + f1.y*f1.y + f1.z*f1.z + f1.w*f1.w;
        __half2 h0 = __floats2half2_rn(f0.x, f0.y);
        __half2 h1 = __floats2half2_rn(f0.z, f0.w);
        __half2 h2 = __floats2half2_rn(f1.x, f1.y);
        __half2 h3 = __floats2half2_rn(f1.z, f1.w);
        uint4 pk = {*reinterpret_cast<uint32_t*>(&h0), *reinterpret_cast<uint32_t*>(&h1),
                    *reinterpret_cast<uint32_t*>(&h2), *reinterpret_cast<uint32_t*>(&h3)};
        *reinterpret_cast<uint4*>(&g_whf[(size_t)v * DDIM + lane * 8]) = pk;
#pragma unroll
        for (int o = 16; o; o >>= 1) s += __shfl_xor_sync(0xFFFFFFFFu, s, o);
        if (lane == 0) g_wsq[v] = s;
        return;
    }
    int qp = q - 1569;
    int k0 = (qp & 7) * 32, s0 = ((qp >> 3) & 127) * 32, b = qp >> 10;
    int tx = tid & 31, ty = tid >> 5;             // (32, 8)
#pragma unroll
    for (int i = 0; i < 4; ++i)
        t[ty + i * 8][tx] = x[(size_t)b * 1048576 + (size_t)(k0 + ty + i * 8) * SPAT + s0 + tx];
    __syncthreads();
#pragma unroll
    for (int i = 0; i < 4; ++i) {
        int r = b * SPAT + s0 + ty + i * 8;
        g_ahf[(size_t)r * DDIM + k0 + tx] = __float2half_rn(t[tx][ty + i * 8]);
    }
}

// ---------------------------------------------------------------------------
// fp16-accum HMMA GEMM: CTA 128x128, 8 warps of 64x32, K-chunk=64, 3-stage
// x 32KB pipeline, 96KB dyn smem. Epilogue: plain-store per-row tile max.
#define STAGE_B 32768
#define SMEM_DYN (3 * STAGE_B)

__global__ __launch_bounds__(256, 2) void k_gemm() {
    extern __shared__ __align__(16) char sm[];
    const int tid = threadIdx.x;
    const int lane = tid & 31, wid = tid >> 5;
    const int wm = wid & 1, wn = wid >> 1;        // warp tile 64m x 32n
    const int jbase = blockIdx.x * 128;
    const int rbase = blockIdx.y * 128;
    const uint32_t smb = smem_u32(sm);

    const int sel = lane >> 3, rin = lane & 7;

    uint32_t baseA[4]; int vA[4];
#pragma unroll
    for (int i = 0; i < 4; ++i) {
        int row = wm * 64 + i * 16 + rin + ((sel & 1) << 3);
        baseA[i] = (uint32_t)(row * 128);
        vA[i] = row & 7;
    }
    const int hA = sel >> 1;
    uint32_t baseB[2]; int vB[2];
#pragma unroll
    for (int p = 0; p < 2; ++p) {
        int row = wn * 32 + p * 16 + rin + ((sel >> 1) << 3);
        baseB[p] = (uint32_t)(16384 + row * 128);
        vB[p] = row & 7;
    }
    const int hB = sel & 1;

    const __half* sp[8];
    uint32_t doff[8];
#pragma unroll
    for (int e = 0; e < 8; ++e) {
        int idx = tid + (e & 3) * 256;             // 0..1023
        int row = idx >> 3, c = idx & 7;
        if (e < 4) {
            sp[e] = g_ahf + (size_t)(rbase + row) * DDIM + c * 8;
            doff[e] = (uint32_t)(row * 128 + ((c ^ (row & 7)) << 4));
        } else {
            sp[e] = g_whf + (size_t)(jbase + row) * DDIM + c * 8;
            doff[e] = (uint32_t)(16384 + row * 128 + ((c ^ (row & 7)) << 4));
        }
    }

    uint32_t acc[4][4][2];
#pragma unroll
    for (int i = 0; i < 4; ++i)
#pragma unroll
        for (int j = 0; j < 4; ++j) { acc[i][j][0] = 0u; acc[i][j][1] = 0u; }

#define LOAD_STAGE(st, ko)                                                \
    do {                                                                  \
        uint32_t sb_ = smb + (st) * STAGE_B;                              \
        _Pragma("unroll")                                                 \
        for (int e = 0; e < 8; ++e) cp16(sb_ + doff[e], sp[e] + (ko));    \
        asm volatile("cp.async.commit_group;" ::: "memory");              \
    } while (0)

    LOAD_STAGE(0, 0);
    LOAD_STAGE(1, 64);

#pragma unroll
    for (int c = 0; c < 4; ++c) {
        if (c < 3) asm volatile("cp.async.wait_group 1;" ::: "memory");
        else       asm volatile("cp.async.wait_group 0;" ::: "memory");
        __syncthreads();
        if (c < 2) LOAD_STAGE(c + 2 - ((c + 2 >= 3) ? 3 : 0), (c + 2) * 64);
        uint32_t sb = smb + (c % 3) * STAGE_B;
#pragma unroll
        for (int ks = 0; ks < 4; ++ks) {
            uint32_t a[4][4], bf[4][2];
#pragma unroll
            for (int i = 0; i < 4; ++i)
                ldm4(a[i], sb + baseA[i] + (((ks * 2 + hA) ^ vA[i]) << 4));
#pragma unroll
            for (int p = 0; p < 2; ++p) {
                uint32_t r4[4];
                ldm4(r4, sb + baseB[p] + (((ks * 2 + hB) ^ vB[p]) << 4));
                bf[2 * p][0] = r4[0]; bf[2 * p][1] = r4[1];
                bf[2 * p + 1][0] = r4[2]; bf[2 * p + 1][1] = r4[3];
            }
#pragma unroll
            for (int i = 0; i < 4; ++i)
#pragma unroll
                for (int j = 0; j < 4; ++j)
                    mma16816h(acc[i][j], a[i], bf[j]);
        }
    }
#undef LOAD_STAGE

    // epilogue: scores = acc - 0.5*wsq; store bf16; per-row tile max (no atomics)
    const int lq = lane >> 2, lr = lane & 3;
    float bv[8];
#pragma unroll
    for (int s = 0; s < 8; ++s) bv[s] = -3.4e38f;

#pragma unroll
    for (int j = 0; j < 4; ++j) {
        int col = jbase + wn * 32 + j * 8 + lr * 2;
        float2 wq = *reinterpret_cast<const float2*>(&g_wsq[col]);
#pragma unroll
        for (int i = 0; i < 4; ++i) {
#pragma unroll
            for (int h = 0; h < 2; ++h) {
                float2 f = __half22float2(*reinterpret_cast<__half2*>(&acc[i][j][h]));
                float s0 = f.x - 0.5f * wq.x;
                float s1 = f.y - 0.5f * wq.y;
                int grow = rbase + wm * 64 + i * 16 + lq + h * 8;
                __nv_bfloat162 pr = __floats2bfloat162_rn(s0, s1);
                st_cs32(&g_scores[(size_t)grow * VCODES + col],
                        *reinterpret_cast<uint32_t*>(&pr));
                int slot = i * 2 + h;
                bv[slot] = fmaxf(bv[slot], fmaxf(s0, s1));
            }
        }
    }
#pragma unroll
    for (int s = 0; s < 8; ++s) {
#pragma unroll
        for (int o = 1; o < 4; o <<= 1)
            bv[s] = fmaxf(bv[s], __shfl_xor_sync(0xFFFFFFFFu, bv[s], o));
    }
    __syncthreads();                              // done with stage smem
    float* red = (float*)sm;                      // 128 x 4 floats
    if (lr == 0) {
#pragma unroll
        for (int s = 0; s < 8; ++s) {
            int rl = wm * 64 + (s >> 1) * 16 + lq + (s & 1) * 8;
            red[rl * 4 + wn] = bv[s];
        }
    }
    __syncthreads();
    if (tid < 128) {
        float m = fmaxf(fmaxf(red[tid * 4], red[tid * 4 + 1]),
                        fmaxf(red[tid * 4 + 2], red[tid * 4 + 3]));
        g_tilemax[(rbase + tid) * NTILES + blockIdx.x] = enc_f(m);
    }
}

// ---------------------------------------------------------------------------
// Repair: thr from tile maxima; scan flagged tiles' scores; exact fp32
// recompute of candidates. Ascending-j order preserves first-index tie-break.
__global__ void k_repair(const float* __restrict__ x, const float* __restrict__ w,
                         float* __restrict__ out) {
    int r = blockIdx.x * 8 + (threadIdx.x >> 5);
    int lane = threadIdx.x & 31;
    const unsigned* tmrow = g_tilemax + r * NTILES;
    unsigned t0 = tmrow[lane], t1 = tmrow[lane + 32];
    unsigned tmx = max(t0, t1);                   // monotone encoding: u32 max ok
#pragma unroll
    for (int o = 16; o; o >>= 1) tmx = max(tmx, __shfl_xor_sync(0xFFFFFFFFu, tmx, o));
    float thr = dec_f(tmx) - MARGIN;
    int b = r >> 12, s = r & 4095;
    const float* xb = x + (size_t)b * 1048576 + s;
    float bestv = -3.4e38f;
    int   bestj = 0;
    const __nv_bfloat16* srow = g_scores + (size_t)r * VCODES;
#pragma unroll
    for (int half = 0; half < 2; ++half) {
        unsigned tm = half ? t1 : t0;
        unsigned act = __ballot_sync(0xFFFFFFFFu, dec_f(tm) >= thr);
        while (act) {
            int t = __ffs(act) - 1; act &= act - 1;
            int tile = half * 32 + t;
            uint2 v = *reinterpret_cast<const uint2*>(srow + tile * 128 + lane * 4);
            unsigned m = 0;
            unsigned wds[2] = {v.x, v.y};
#pragma unroll
            for (int q = 0; q < 2; ++q) {
                __nv_bfloat162 h2 = *reinterpret_cast<__nv_bfloat162*>(&wds[q]);
                float2 f = __bfloat1622float2(h2);
                if (f.x >= thr) m |= 1u << (2 * q);
                if (f.y >= thr) m |= 1u << (2 * q + 1);
            }
            unsigned act2 = __ballot_sync(0xFFFFFFFFu, m != 0);
            while (act2) {
                int src = __ffs(act2) - 1; act2 &= act2 - 1;
                unsigned mm = __shfl_sync(0xFFFFFFFFu, m, src);
                while (mm) {
                    int bit = __ffs(mm) - 1; mm &= mm - 1;
                    int j = tile * 128 + src * 4 + bit;
                    const float* wr = w + (size_t)j * DDIM;
                    float p = 0.0f;
#pragma unroll
                    for (int q = 0; q < 8; ++q) {
                        int k = lane + q * 32;
                        p += xb[(size_t)k * SPAT] * wr[k];
                    }
#pragma unroll
                    for (int o = 16; o; o >>= 1) p += __shfl_xor_sync(0xFFFFFFFFu, p, o);
                    float sc = p - 0.5f * g_wsq[j];
                    if (sc > bestv) { bestv = sc; bestj = j; }
                }
            }
        }
    }
    if (lane == 0) {
        g_idx[r] = bestj;
        out[O_IDX + r] = (float)bestj;
        atomicAdd(&g_counts[bestj], 1.0f);
    }
}

// ---------------------------------------------------------------------------
// quant write + enc_sum vector reductions + quant_diff. Grid 4096 = 256
// spatial-chunks x 16 d-groups of 16. Thread handles 2 d-quads.
__global__ void k_assign(const float* __restrict__ x, const float* __restrict__ w,
                         float* __restrict__ out) {
    __shared__ int sidx[128];
    __shared__ float red[8];
    int bi = blockIdx.x;
    int tid = threadIdx.x;
    int sc = bi & 255, dgp = bi >> 8;             // spatial chunk, d-group (0..15)
    int b = sc >> 5, s0 = (sc & 31) * 128;
    int ts = tid & 127, dh = tid >> 7;
    if (tid < 128) sidx[tid] = g_idx[b * SPAT + s0 + tid];
    __syncthreads();
    int j = sidx[ts];
    const float* wr = w + (size_t)j * DDIM;
    float* er = g_encsum + (size_t)j * DDIM;
    size_t basex = (size_t)b * 1048576 + s0 + ts;
    int d0 = dgp * 16 + dh * 4;                   // quads at d0, d0+8
    float qd = 0.0f;
#pragma unroll
    for (int k = 0; k < 2; ++k) {
        int d = d0 + k * 8;
        float4 wv = __ldg(reinterpret_cast<const float4*>(wr + d));
        size_t off = basex + (size_t)d * SPAT;
        float x0 = x[off];
        float x1 = x[off + SPAT];
        float x2 = x[off + 2 * SPAT];
        float x3 = x[off + 3 * SPAT];
        out[O_QUANT + off]            = (wv.x - x0) + x0;
        out[O_QUANT + off + SPAT]     = (wv.y - x1) + x1;
        out[O_QUANT + off + 2 * SPAT] = (wv.z - x2) + x2;
        out[O_QUANT + off + 3 * SPAT] = (wv.w - x3) + x3;
        float d0f = x0 - wv.x, d1f = x1 - wv.y, d2f = x2 - wv.z, d3f = x3 - wv.w;
        qd += d0f * d0f + d1f * d1f + d2f * d2f + d3f * d3f;
        red4(er + d, x0, x1, x2, x3);
    }
#pragma unroll
    for (int o = 16; o; o >>= 1) qd += __shfl_xor_sync(0xFFFFFFFFu, qd, o);
    if ((tid & 31) == 0) red[tid >> 5] = qd;
    __syncthreads();
    if (tid == 0) {
        float t = 0.0f;
#pragma unroll
        for (int i = 0; i < 8; ++i) t += red[i];
        atomicAdd(&g_qd, t);
    }
}

// ---------------------------------------------------------------------------
// EMA update: thread handles 4 consecutive d (vector loads, scalar stores —
// O_ZAVG/O_NEWW are odd offsets so 16B stores would be misaligned).
__global__ void k_update(const float* __restrict__ N, const float* __restrict__ z_avg,
                         float* __restrict__ out) {
    int qd4 = blockIdx.x * 256 + threadIdx.x;     // quad index, covers 524288
    int i = qd4 * 4;
    int v = i >> 8;
    float gamma = 0.99f, om = 0.01f, eps = 1e-7f;
    float n  = gamma * g_sumN + om * (float)MROWS;
    float nN = gamma * N[v] + om * g_counts[v];
    float4 es = *reinterpret_cast<const float4*>(&g_encsum[i]);
    float4 za = __ldg(reinterpret_cast<const float4*>(z_avg + i));
    float z0 = gamma * za.x + om * es.x;
    float z1 = gamma * za.y + om * es.y;
    float z2 = gamma * za.z + om * es.z;
    float z3 = gamma * za.w + om * es.w;
    out[O_ZAVG + i]     = z0;
    out[O_ZAVG + i + 1] = z1;
    out[O_ZAVG + i + 2] = z2;
    out[O_ZAVG + i + 3] = z3;
    float wq = (nN + eps) / (n + (float)VCODES * eps) * n;
    out[O_NEWW + i]     = z0 / wq;
    out[O_NEWW + i + 1] = z1 / wq;
    out[O_NEWW + i + 2] = z2 / wq;
    out[O_NEWW + i + 3] = z3 / wq;
    if ((i & 255) == 0) out[O_NEWN + v] = nN;
    if (i == 0) out[O_QD] = g_qd * (1.0f / 8388608.0f);
}

// ---------------------------------------------------------------------------
extern "C" void kernel_launch(void* const* d_in, const int* in_sizes, int n_in,
                              void* d_out, int out_size) {
    const float* x    = (const float*)d_in[0];
    const float* w    = (const float*)d_in[1];
    const float* N    = (const float*)d_in[2];
    const float* zavg = (const float*)d_in[3];
    float* out = (float*)d_out;

    cudaFuncSetAttribute(k_gemm, cudaFuncAttributeMaxDynamicSharedMemorySize, SMEM_DYN);

    k_prep<<<9761, 256>>>(x, w, N);
    k_gemm<<<dim3(VCODES / 128, MROWS / 128), 256, SMEM_DYN>>>();
    k_repair<<<MROWS / 8, 256>>>(x, w, out);
    k_assign<<<4096, 256>>>(x, w, out);
    k_update<<<2048, 256>>>(N, zavg, out);
}